// round 7
// baseline (speedup 1.0000x reference)
#include <cuda_runtime.h>
#include <cuda_bf16.h>
#include <cstdint>

// ---------------- problem constants ----------------
#define BHALF 4096
#define NROWS 8192
#define DDIM  1024
#define INVT  10.0f
// stored values are (16 * x); dot of stored = 256 * sim
#define QS 16.0f
#define Y_SCALE2 (14.4269504088896341f / 256.0f)   // INVT*log2e / 256
#define POS_SCALE (10.0f / 256.0f)

// ---------------- tiling ----------------
#define KC 64                 // K elems (bytes) per pipeline stage
#define ROW_B 80              // 64 fp8 = 64B + 16B pad (conflict-free ldmatrix)
#define A_B (128 * ROW_B)                 // 10240
#define STAGE_BYTES (2 * A_B)             // 20480
#define NSTAGES 3
#define SMEM_TOTAL (NSTAGES * STAGE_BYTES) // 61440
#define NBLK 64
#define NTILES (NBLK * (NBLK + 1) / 2)    // 2080

__device__ __align__(16) uint8_t g_f8[NROWS * DDIM];   // quantized e4m3 (8MB)
__device__ float g_rowsum[NROWS];
__device__ float g_pos[NROWS];

// ---------------------------------------------------------------------------
__device__ __forceinline__ float fexp2f(float y) {
    float t = y + 12582912.0f;
    int   i = __float_as_int(t);
    float f = y - (t - 12582912.0f);
    float p = 1.33335581e-3f;
    p = fmaf(p, f, 9.61812910e-3f);
    p = fmaf(p, f, 5.55041086e-2f);
    p = fmaf(p, f, 2.40226507e-1f);
    p = fmaf(p, f, 6.93147182e-1f);
    p = fmaf(p, f, 1.0f);
    return p * __int_as_float((i + (127 - 0x4B400000)) << 23);
}

// pack 2 floats -> e4m3x2 (lo = first arg)
__device__ __forceinline__ unsigned short cvt_e4m3x2(float lo, float hi) {
    unsigned short r;
    asm("cvt.rn.satfinite.e4m3x2.f32 %0, %1, %2;" : "=h"(r) : "f"(hi), "f"(lo));
    return r;
}

// ---------------------------------------------------------------------------
// Kernel 1: row L2-normalize -> e4m3 (x16); one warp per row
// ---------------------------------------------------------------------------
__global__ void __launch_bounds__(256) norm_kernel(const float* __restrict__ v1,
                                                   const float* __restrict__ v2) {
    const int lane = threadIdx.x & 31;
    const int row  = blockIdx.x * 8 + (threadIdx.x >> 5);
    const float* src = (row < BHALF) ? (v1 + (size_t)row * DDIM)
                                     : (v2 + (size_t)(row - BHALF) * DDIM);
    const float4* src4 = reinterpret_cast<const float4*>(src);
    float4 v[8];
    float ss = 0.0f;
    #pragma unroll
    for (int i = 0; i < 8; i++) {
        v[i] = src4[lane + i * 32];
        ss += v[i].x*v[i].x + v[i].y*v[i].y + v[i].z*v[i].z + v[i].w*v[i].w;
    }
    #pragma unroll
    for (int o = 16; o; o >>= 1) ss += __shfl_xor_sync(0xFFFFFFFFu, ss, o);
    float scale = QS / fmaxf(sqrtf(ss), 1e-12f);

    unsigned* dst = reinterpret_cast<unsigned*>(g_f8 + (size_t)row * DDIM);
    #pragma unroll
    for (int i = 0; i < 8; i++) {
        unsigned short p0 = cvt_e4m3x2(v[i].x * scale, v[i].y * scale);
        unsigned short p1 = cvt_e4m3x2(v[i].z * scale, v[i].w * scale);
        dst[lane + i * 32] = (unsigned)p0 | ((unsigned)p1 << 16);
    }
    if (lane == 0) { g_rowsum[row] = 0.0f; g_pos[row] = 0.0f; }
}

// ---------------------------------------------------------------------------
// PTX helpers
// ---------------------------------------------------------------------------
__device__ __forceinline__ void cp_async16(unsigned dst, const void* src) {
    asm volatile("cp.async.cg.shared.global [%0], [%1], 16;" :: "r"(dst), "l"(src) : "memory");
}
__device__ __forceinline__ void cp_commit() {
    asm volatile("cp.async.commit_group;" ::: "memory");
}
__device__ __forceinline__ void ldmatrix_x4(unsigned& r0, unsigned& r1,
                                            unsigned& r2, unsigned& r3, unsigned addr) {
    asm volatile("ldmatrix.sync.aligned.m8n8.x4.shared.b16 {%0,%1,%2,%3}, [%4];"
                 : "=r"(r0), "=r"(r1), "=r"(r2), "=r"(r3) : "r"(addr));
}
__device__ __forceinline__ void mma_fp8(float& d0, float& d1, float& d2, float& d3,
                                        unsigned a0, unsigned a1, unsigned a2, unsigned a3,
                                        unsigned b0, unsigned b1) {
    asm volatile("mma.sync.aligned.m16n8k32.row.col.f32.e4m3.e4m3.f32 "
                 "{%0,%1,%2,%3}, {%4,%5,%6,%7}, {%8,%9}, {%0,%1,%2,%3};"
                 : "+f"(d0), "+f"(d1), "+f"(d2), "+f"(d3)
                 : "r"(a0), "r"(a1), "r"(a2), "r"(a3), "r"(b0), "r"(b1));
}

// Load one K-chunk: A = rows of rb-block, B = rows of cb-block (128 x 64B each)
__device__ __forceinline__ void load_tiles(unsigned smem_base, int stage,
                                           int rb, int cb, int kc, int tid) {
    unsigned base = smem_base + stage * STAGE_BYTES;
    const uint8_t* fn = g_f8;
    #pragma unroll
    for (int it = 0; it < 4; it++) {
        int c   = tid + it * 256;          // 0..1023
        int isB = c >> 9;
        int cl  = c & 511;
        int r   = cl >> 2;                 // row 0..127
        int p   = cl & 3;                  // 16B chunk 0..3
        int srow = (isB ? cb : rb) * 128 + r;
        const void* src = fn + (size_t)srow * DDIM + kc * KC + p * 16;
        unsigned dst = base + isB * A_B + r * ROW_B + p * 16;
        cp_async16(dst, src);
    }
}

// ---------------------------------------------------------------------------
// Kernel 2: symmetric fused fp8 sim GEMM + exp row/col sums
// grid NTILES (128x128 tile per CTA), 256 threads, warp tile 32x64
// ---------------------------------------------------------------------------
__global__ void __launch_bounds__(256, 2) simexp_kernel() {
    extern __shared__ char smem[];
    unsigned smem_base = (unsigned)__cvta_generic_to_shared(smem);

    const int tid  = threadIdx.x;
    const int lane = tid & 31;
    const int wid  = tid >> 5;
    const int wm   = wid & 3;          // warp row 0..3 (32 rows each)
    const int wn   = wid >> 2;         // warp col 0..1 (64 cols each)

    // decode upper-triangle tile index -> (rb, cb), cb >= rb
    const int t = blockIdx.x;
    int rb = (int)((129.0f - sqrtf(129.0f*129.0f - 8.0f*(float)t)) * 0.5f);
    if (rb > 63) rb = 63;
    if (rb < 0)  rb = 0;
    int off = rb*64 - rb*(rb-1)/2;
    while (off > t)                 { rb--; off = rb*64 - rb*(rb-1)/2; }
    while (off + (NBLK - rb) <= t)  { off += NBLK - rb; rb++; }
    const int cb = rb + (t - off);
    const bool is_diag = (cb == rb);
    const bool is_pos  = (cb == rb + 32);

    // ldmatrix lane base addresses (stage-relative); rows are 64B (32 b16) wide
    const unsigned a_base = smem_base + (wm*32 + (lane & 15)) * ROW_B + (lane >> 4) * 16;
    const unsigned b_base = smem_base + A_B
                          + (wn*64 + (lane & 7) + ((lane >> 4) << 3)) * ROW_B
                          + ((lane >> 3) & 1) * 16;

    float acc[2][8][4];
    #pragma unroll
    for (int mf = 0; mf < 2; mf++)
        #pragma unroll
        for (int j = 0; j < 8; j++)
            #pragma unroll
            for (int e = 0; e < 4; e++) acc[mf][j][e] = 0.0f;

    const int NCHUNK = DDIM / KC;    // 16
    load_tiles(smem_base, 0, rb, cb, 0, tid); cp_commit();
    load_tiles(smem_base, 1, rb, cb, 1, tid); cp_commit();

    for (int kc = 0; kc < NCHUNK; kc++) {
        if (kc < NCHUNK - 1) asm volatile("cp.async.wait_group 1;" ::: "memory");
        else                 asm volatile("cp.async.wait_group 0;" ::: "memory");
        __syncthreads();
        if (kc + 2 < NCHUNK) {
            load_tiles(smem_base, (kc + 2) % NSTAGES, rb, cb, kc + 2, tid);
            cp_commit();
        }
        const unsigned sA = a_base + (kc % NSTAGES) * STAGE_BYTES;
        const unsigned sB = b_base + (kc % NSTAGES) * STAGE_BYTES;
        #pragma unroll
        for (int ks = 0; ks < 2; ks++) {        // 2 x k32 per 64B chunk
            unsigned a[2][4];
            #pragma unroll
            for (int mf = 0; mf < 2; mf++)
                ldmatrix_x4(a[mf][0], a[mf][1], a[mf][2], a[mf][3],
                            sA + mf * (16 * ROW_B) + ks * 32);
            unsigned b[2][4];
            ldmatrix_x4(b[0][0], b[0][1], b[0][2], b[0][3], sB + ks * 32);
            #pragma unroll
            for (int nf = 0; nf < 4; nf++) {    // 16 cols per ldmatrix (2 n8 tiles)
                const int cur = nf & 1;
                if (nf < 3)
                    ldmatrix_x4(b[cur^1][0], b[cur^1][1], b[cur^1][2], b[cur^1][3],
                                sB + (nf + 1) * (16 * ROW_B) + ks * 32);
                #pragma unroll
                for (int mf = 0; mf < 2; mf++) {
                    mma_fp8(acc[mf][2*nf][0],   acc[mf][2*nf][1],
                            acc[mf][2*nf][2],   acc[mf][2*nf][3],
                            a[mf][0], a[mf][1], a[mf][2], a[mf][3],
                            b[cur][0], b[cur][1]);
                    mma_fp8(acc[mf][2*nf+1][0], acc[mf][2*nf+1][1],
                            acc[mf][2*nf+1][2], acc[mf][2*nf+1][3],
                            a[mf][0], a[mf][1], a[mf][2], a[mf][3],
                            b[cur][2], b[cur][3]);
                }
            }
        }
    }

    // ---------------- epilogue ----------------
    float rs[2][2] = {{0.f,0.f},{0.f,0.f}};   // [mf][lo/hi] row sums
    float cs[8][2];                            // [j][parity] col sums
    #pragma unroll
    for (int j = 0; j < 8; j++) { cs[j][0] = 0.f; cs[j][1] = 0.f; }

    const int rq = lane >> 2;      // 0..7
    const int cq = (lane & 3) * 2; // 0,2,4,6

    #pragma unroll
    for (int mf = 0; mf < 2; mf++) {
        #pragma unroll
        for (int j = 0; j < 8; j++) {
            #pragma unroll
            for (int e = 0; e < 4; e++) {
                float a  = acc[mf][j][e];
                int r_local = wm*32 + mf*16 + rq + ((e & 2) ? 8 : 0);
                int c_local = wn*64 + j*8 + cq + (e & 1);
                float ev = fexp2f(a * Y_SCALE2);
                if (is_diag && r_local == c_local) ev = 0.0f;
                rs[mf][e >> 1] += ev;
                cs[j][e & 1]   += ev;
                if (is_pos && r_local == c_local) {
                    float pv = a * POS_SCALE;
                    atomicAdd(&g_pos[rb*128 + r_local], pv);
                    atomicAdd(&g_pos[cb*128 + c_local], pv);
                }
            }
        }
    }

    // row sums: reduce over lane&3 (cols), write rows of rb block
    #pragma unroll
    for (int mf = 0; mf < 2; mf++) {
        #pragma unroll
        for (int h = 0; h < 2; h++) {
            float v = rs[mf][h];
            v += __shfl_xor_sync(0xFFFFFFFFu, v, 1);
            v += __shfl_xor_sync(0xFFFFFFFFu, v, 2);
            if ((lane & 3) == 0)
                atomicAdd(&g_rowsum[rb*128 + wm*32 + mf*16 + rq + h*8], v);
        }
    }

    // col sums: reduce over lane>>2 (rows), write rows of cb block (symmetry)
    if (!is_diag) {
        #pragma unroll
        for (int j = 0; j < 8; j++) {
            #pragma unroll
            for (int par = 0; par < 2; par++) {
                float v = cs[j][par];
                v += __shfl_xor_sync(0xFFFFFFFFu, v, 4);
                v += __shfl_xor_sync(0xFFFFFFFFu, v, 8);
                v += __shfl_xor_sync(0xFFFFFFFFu, v, 16);
                if (lane < 4)
                    atomicAdd(&g_rowsum[cb*128 + wn*64 + j*8 + lane*2 + par], v);
            }
        }
    }
}

// ---------------------------------------------------------------------------
// Kernel 3: loss = mean(log(rowsum_i) - pos_i)
// ---------------------------------------------------------------------------
__global__ void __launch_bounds__(256) loss_kernel(float* __restrict__ out) {
    __shared__ double red[256];
    double s = 0.0;
    for (int i = threadIdx.x; i < NROWS; i += 256)
        s += (double)(logf(g_rowsum[i]) - g_pos[i]);
    red[threadIdx.x] = s;
    __syncthreads();
    for (int k = 128; k > 0; k >>= 1) {
        if (threadIdx.x < k) red[threadIdx.x] += red[threadIdx.x + k];
        __syncthreads();
    }
    if (threadIdx.x == 0) out[0] = (float)(red[0] / (double)NROWS);
}

// ---------------------------------------------------------------------------
extern "C" void kernel_launch(void* const* d_in, const int* in_sizes, int n_in,
                              void* d_out, int out_size) {
    const float* v1 = (const float*)d_in[0];
    const float* v2 = (const float*)d_in[1];
    float* out = (float*)d_out;

    cudaFuncSetAttribute(simexp_kernel,
                         cudaFuncAttributeMaxDynamicSharedMemorySize, SMEM_TOTAL);

    norm_kernel<<<NROWS / 8, 256>>>(v1, v2);
    simexp_kernel<<<NTILES, 256, SMEM_TOTAL>>>();
    loss_kernel<<<1, 256>>>(out);
}

// round 8
// speedup vs baseline: 1.1303x; 1.1303x over previous
#include <cuda_runtime.h>
#include <cuda_bf16.h>
#include <cstdint>

// ---------------- problem constants ----------------
#define BHALF 4096
#define NROWS 8192
#define DDIM  1024
#define INVT  10.0f
#define Y_SCALE 14.4269504088896341f   // INVT * log2(e)

// ---------------- tiling ----------------
#define KC 64                 // K elems per pipeline stage
#define ROW_BYTES 144         // 64 bf16 = 128B + 16B pad
#define A_BYTES (128 * ROW_BYTES)          // 18432
#define STAGE_BYTES (2 * A_BYTES)          // 36864
#define NSTAGES 3
#define SMEM_TOTAL (NSTAGES * STAGE_BYTES) // 110592
#define NBLK 64               // 8192 / 128
#define NTILES (NBLK * (NBLK + 1) / 2)     // 2080 upper-triangle tiles

__device__ __align__(16) __nv_bfloat16 g_fn[NROWS * DDIM];  // normalized bf16 (16MB)
__device__ float g_rowsum[NROWS];
__device__ float g_pos[NROWS];

// ---------------------------------------------------------------------------
__device__ __forceinline__ float fexp2f(float y) {
    float t = y + 12582912.0f;
    int   i = __float_as_int(t);
    float f = y - (t - 12582912.0f);
    float p = 1.33335581e-3f;
    p = fmaf(p, f, 9.61812910e-3f);
    p = fmaf(p, f, 5.55041086e-2f);
    p = fmaf(p, f, 2.40226507e-1f);
    p = fmaf(p, f, 6.93147182e-1f);
    p = fmaf(p, f, 1.0f);
    return p * __int_as_float((i + (127 - 0x4B400000)) << 23);
}

// ---------------------------------------------------------------------------
// Kernel 1: row L2-normalize -> bf16 (one warp per row, 128-thr CTAs for occ)
// Also zeroes accumulators and out[0].
// ---------------------------------------------------------------------------
__global__ void __launch_bounds__(128) norm_kernel(const float* __restrict__ v1,
                                                   const float* __restrict__ v2,
                                                   float* __restrict__ out) {
    const int lane = threadIdx.x & 31;
    const int row  = blockIdx.x * 4 + (threadIdx.x >> 5);
    const float* src = (row < BHALF) ? (v1 + (size_t)row * DDIM)
                                     : (v2 + (size_t)(row - BHALF) * DDIM);
    const float4* src4 = reinterpret_cast<const float4*>(src);
    float4 v[8];
    float ss = 0.0f;
    #pragma unroll
    for (int i = 0; i < 8; i++) {
        v[i] = src4[lane + i * 32];
        ss += v[i].x*v[i].x + v[i].y*v[i].y + v[i].z*v[i].z + v[i].w*v[i].w;
    }
    #pragma unroll
    for (int o = 16; o; o >>= 1) ss += __shfl_xor_sync(0xFFFFFFFFu, ss, o);
    float scale = 1.0f / fmaxf(sqrtf(ss), 1e-12f);

    __nv_bfloat162* dst = reinterpret_cast<__nv_bfloat162*>(g_fn + (size_t)row * DDIM);
    #pragma unroll
    for (int i = 0; i < 8; i++) {
        __nv_bfloat162 h0, h1;
        h0.x = __float2bfloat16(v[i].x * scale); h0.y = __float2bfloat16(v[i].y * scale);
        h1.x = __float2bfloat16(v[i].z * scale); h1.y = __float2bfloat16(v[i].w * scale);
        int idx = lane + i * 32;
        dst[idx * 2 + 0] = h0;
        dst[idx * 2 + 1] = h1;
    }
    if (lane == 0) { g_rowsum[row] = 0.0f; g_pos[row] = 0.0f; }
    if (row == 0 && lane == 0) out[0] = 0.0f;
}

// ---------------------------------------------------------------------------
// PTX helpers
// ---------------------------------------------------------------------------
__device__ __forceinline__ void cp_async16(unsigned dst, const void* src) {
    asm volatile("cp.async.cg.shared.global [%0], [%1], 16;" :: "r"(dst), "l"(src) : "memory");
}
__device__ __forceinline__ void cp_commit() {
    asm volatile("cp.async.commit_group;" ::: "memory");
}
__device__ __forceinline__ void ldmatrix_x4(unsigned& r0, unsigned& r1,
                                            unsigned& r2, unsigned& r3, unsigned addr) {
    asm volatile("ldmatrix.sync.aligned.m8n8.x4.shared.b16 {%0,%1,%2,%3}, [%4];"
                 : "=r"(r0), "=r"(r1), "=r"(r2), "=r"(r3) : "r"(addr));
}
__device__ __forceinline__ void mma_bf16(float& d0, float& d1, float& d2, float& d3,
                                         unsigned a0, unsigned a1, unsigned a2, unsigned a3,
                                         unsigned b0, unsigned b1) {
    asm volatile("mma.sync.aligned.m16n8k16.row.col.f32.bf16.bf16.f32 "
                 "{%0,%1,%2,%3}, {%4,%5,%6,%7}, {%8,%9}, {%0,%1,%2,%3};"
                 : "+f"(d0), "+f"(d1), "+f"(d2), "+f"(d3)
                 : "r"(a0), "r"(a1), "r"(a2), "r"(a3), "r"(b0), "r"(b1));
}

// Load one K-chunk: A = rows of rb-block, B = rows of cb-block (both 128 x 64)
__device__ __forceinline__ void load_tiles(unsigned smem_base, int stage,
                                           int rb, int cb, int kc, int tid) {
    unsigned base = smem_base + stage * STAGE_BYTES;
    const __nv_bfloat16* fn = g_fn;
    #pragma unroll
    for (int it = 0; it < 8; it++) {
        int c   = tid + it * 256;          // 0..2047
        int isB = c >> 10;
        int cl  = c & 1023;
        int r   = cl >> 3;
        int p   = cl & 7;
        int srow = (isB ? cb : rb) * 128 + r;
        const void* src = fn + (size_t)srow * DDIM + kc * KC + p * 8;
        unsigned dst = base + isB * A_BYTES + r * ROW_BYTES + p * 16;
        cp_async16(dst, src);
    }
}

// ---------------------------------------------------------------------------
// Kernel 2: symmetric fused sim GEMM + exp row/col sums
// grid NTILES (one 128x128 upper-triangle tile per CTA), 256 threads
// warp grid: 4 (m) x 2 (n); warp tile 32 x 64; A+B fragment double buffering
// ---------------------------------------------------------------------------
__global__ void __launch_bounds__(256, 2) simexp_kernel() {
    extern __shared__ char smem[];
    unsigned smem_base = (unsigned)__cvta_generic_to_shared(smem);

    const int tid  = threadIdx.x;
    const int lane = tid & 31;
    const int wid  = tid >> 5;
    const int wm   = wid & 3;          // warp row 0..3 (32 rows each)
    const int wn   = wid >> 2;         // warp col 0..1 (64 cols each)

    // decode upper-triangle tile index -> (rb, cb), cb >= rb
    const int t = blockIdx.x;
    int rb = (int)((129.0f - sqrtf(129.0f*129.0f - 8.0f*(float)t)) * 0.5f);
    if (rb > 63) rb = 63;
    if (rb < 0)  rb = 0;
    int off = rb*64 - rb*(rb-1)/2;
    while (off > t)                 { rb--; off = rb*64 - rb*(rb-1)/2; }
    while (off + (NBLK - rb) <= t)  { off += NBLK - rb; rb++; }
    const int cb = rb + (t - off);
    const bool is_diag = (cb == rb);
    const bool is_pos  = (cb == rb + 32);

    // ldmatrix lane base addresses (stage-relative)
    const unsigned a_base = smem_base + (wm*32 + (lane & 15)) * ROW_BYTES + (lane >> 4) * 16;
    const unsigned b_base = smem_base + A_BYTES
                          + (wn*64 + (lane & 7) + ((lane >> 4) << 3)) * ROW_BYTES
                          + ((lane >> 3) & 1) * 16;

    float acc[2][8][4];
    #pragma unroll
    for (int mf = 0; mf < 2; mf++)
        #pragma unroll
        for (int j = 0; j < 8; j++)
            #pragma unroll
            for (int e = 0; e < 4; e++) acc[mf][j][e] = 0.0f;

    const int NCHUNK = DDIM / KC;    // 16
    load_tiles(smem_base, 0, rb, cb, 0, tid); cp_commit();
    load_tiles(smem_base, 1, rb, cb, 1, tid); cp_commit();

    for (int kc = 0; kc < NCHUNK; kc++) {
        if (kc < NCHUNK - 1) asm volatile("cp.async.wait_group 1;" ::: "memory");
        else                 asm volatile("cp.async.wait_group 0;" ::: "memory");
        __syncthreads();
        if (kc + 2 < NCHUNK) {
            load_tiles(smem_base, (kc + 2) % NSTAGES, rb, cb, kc + 2, tid);
            cp_commit();
        }
        const unsigned sA = a_base + (kc % NSTAGES) * STAGE_BYTES;
        const unsigned sB = b_base + (kc % NSTAGES) * STAGE_BYTES;

        unsigned a[2][2][4];   // [buf][mf][frag] — double-buffered across ks
        #pragma unroll
        for (int mf = 0; mf < 2; mf++)
            ldmatrix_x4(a[0][mf][0], a[0][mf][1], a[0][mf][2], a[0][mf][3],
                        sA + mf * (16 * ROW_BYTES));

        #pragma unroll
        for (int ks = 0; ks < 4; ks++) {
            const int ab = ks & 1;
            unsigned b[2][4];
            ldmatrix_x4(b[0][0], b[0][1], b[0][2], b[0][3], sB + ks * 32);
            if (ks < 3) {
                #pragma unroll
                for (int mf = 0; mf < 2; mf++)
                    ldmatrix_x4(a[ab^1][mf][0], a[ab^1][mf][1],
                                a[ab^1][mf][2], a[ab^1][mf][3],
                                sA + mf * (16 * ROW_BYTES) + (ks + 1) * 32);
            }
            #pragma unroll
            for (int nf = 0; nf < 4; nf++) {
                const int cur = nf & 1;
                if (nf < 3)
                    ldmatrix_x4(b[cur^1][0], b[cur^1][1], b[cur^1][2], b[cur^1][3],
                                sB + (nf + 1) * (16 * ROW_BYTES) + ks * 32);
                #pragma unroll
                for (int mf = 0; mf < 2; mf++) {
                    mma_bf16(acc[mf][2*nf][0],   acc[mf][2*nf][1],
                             acc[mf][2*nf][2],   acc[mf][2*nf][3],
                             a[ab][mf][0], a[ab][mf][1], a[ab][mf][2], a[ab][mf][3],
                             b[cur][0], b[cur][1]);
                    mma_bf16(acc[mf][2*nf+1][0], acc[mf][2*nf+1][1],
                             acc[mf][2*nf+1][2], acc[mf][2*nf+1][3],
                             a[ab][mf][0], a[ab][mf][1], a[ab][mf][2], a[ab][mf][3],
                             b[cur][2], b[cur][3]);
                }
            }
        }
    }

    // ---------------- epilogue ----------------
    float rs[2][2] = {{0.f,0.f},{0.f,0.f}};   // [mf][lo/hi] row sums
    float cs[8][2];                            // [j][parity] col sums
    #pragma unroll
    for (int j = 0; j < 8; j++) { cs[j][0] = 0.f; cs[j][1] = 0.f; }

    const int rq = lane >> 2;      // 0..7
    const int cq = (lane & 3) * 2; // 0,2,4,6

    #pragma unroll
    for (int mf = 0; mf < 2; mf++) {
        #pragma unroll
        for (int j = 0; j < 8; j++) {
            #pragma unroll
            for (int e = 0; e < 4; e++) {
                float a  = acc[mf][j][e];
                int r_local = wm*32 + mf*16 + rq + ((e & 2) ? 8 : 0);
                int c_local = wn*64 + j*8 + cq + (e & 1);
                float ev = fexp2f(a * Y_SCALE);
                if (is_diag && r_local == c_local) ev = 0.0f;
                rs[mf][e >> 1] += ev;
                cs[j][e & 1]   += ev;
                if (is_pos && r_local == c_local) {
                    float pv = a * INVT;
                    atomicAdd(&g_pos[rb*128 + r_local], pv);
                    atomicAdd(&g_pos[cb*128 + c_local], pv);
                }
            }
        }
    }

    // row sums: reduce over lane&3 (cols), write rows of rb block
    #pragma unroll
    for (int mf = 0; mf < 2; mf++) {
        #pragma unroll
        for (int h = 0; h < 2; h++) {
            float v = rs[mf][h];
            v += __shfl_xor_sync(0xFFFFFFFFu, v, 1);
            v += __shfl_xor_sync(0xFFFFFFFFu, v, 2);
            if ((lane & 3) == 0)
                atomicAdd(&g_rowsum[rb*128 + wm*32 + mf*16 + rq + h*8], v);
        }
    }

    // col sums: reduce over lane>>2 (rows), write rows of cb block (symmetry)
    if (!is_diag) {
        #pragma unroll
        for (int j = 0; j < 8; j++) {
            #pragma unroll
            for (int par = 0; par < 2; par++) {
                float v = cs[j][par];
                v += __shfl_xor_sync(0xFFFFFFFFu, v, 4);
                v += __shfl_xor_sync(0xFFFFFFFFu, v, 8);
                v += __shfl_xor_sync(0xFFFFFFFFu, v, 16);
                if (lane < 4)
                    atomicAdd(&g_rowsum[cb*128 + wn*64 + j*8 + lane*2 + par], v);
            }
        }
    }
}

// ---------------------------------------------------------------------------
// Kernel 3: loss partials -> atomicAdd into out (out zeroed by norm_kernel)
// ---------------------------------------------------------------------------
__global__ void __launch_bounds__(256) loss_kernel(float* __restrict__ out) {
    const int base = blockIdx.x * (NROWS / 32);
    float s = 0.0f;
    for (int i = threadIdx.x; i < NROWS / 32; i += 256) {
        int r = base + i;
        s += logf(g_rowsum[r]) - g_pos[r];
    }
    #pragma unroll
    for (int o = 16; o; o >>= 1) s += __shfl_xor_sync(0xFFFFFFFFu, s, o);
    __shared__ float red[8];
    if ((threadIdx.x & 31) == 0) red[threadIdx.x >> 5] = s;
    __syncthreads();
    if (threadIdx.x == 0) {
        float tot = red[0]+red[1]+red[2]+red[3]+red[4]+red[5]+red[6]+red[7];
        atomicAdd(out, tot * (1.0f / (float)NROWS));
    }
}

// ---------------------------------------------------------------------------
extern "C" void kernel_launch(void* const* d_in, const int* in_sizes, int n_in,
                              void* d_out, int out_size) {
    const float* v1 = (const float*)d_in[0];
    const float* v2 = (const float*)d_in[1];
    float* out = (float*)d_out;

    cudaFuncSetAttribute(simexp_kernel,
                         cudaFuncAttributeMaxDynamicSharedMemorySize, SMEM_TOTAL);

    norm_kernel<<<NROWS / 4, 128>>>(v1, v2, out);
    simexp_kernel<<<NTILES, 256, SMEM_TOTAL>>>();
    loss_kernel<<<32, 256>>>(out);
}